// round 7
// baseline (speedup 1.0000x reference)
#include <cuda_runtime.h>
#include <cuda_bf16.h>
#include <stdint.h>

// out[b] = sum_{s=0}^{199} w_weight[text[s,b]] + bias
// text (200, 2048) row-major, tokens in [0, 50000)
#define S_TOK 200
#define B_PHR 2048
#define V_SZ  50000
#define V_HALF 25000                    // split: low half manual, high half TMA
#define HALF_BYTES (V_HALF * 4)         // 100000 B
#define TMA_CHUNK 50000                 // 2 TMA chunks for the high half
#define PHR_PER_BLK 32
#define NBLK (B_PHR / PHR_PER_BLK)      // 64 blocks, single wave, no clusters
#define NTHR 1024
#define NGRP 32
#define RED_FLOATS (NGRP * PHR_PER_BLK) // 1024
#define SMEM_BYTES (V_SZ * 4 + RED_FLOATS * 4 + 16)

__device__ __forceinline__ uint32_t smem_u32(const void* p) {
    uint32_t a;
    asm("{ .reg .u64 t; cvta.to.shared.u64 t, %1; cvt.u32.u64 %0, t; }"
        : "=r"(a) : "l"(p));
    return a;
}

__global__ __launch_bounds__(NTHR, 1) void MNB_455266533601_kernel(
    const void* __restrict__ text_raw,
    const float* __restrict__ w_weight,
    const float* __restrict__ w_bias,
    float* __restrict__ out)
{
    extern __shared__ float smem[];
    float* sw  = smem;                     // [V_SZ] staged table
    float* red = smem + V_SZ;              // [NGRP][PHR_PER_BLK]
    unsigned long long* mbar =
        (unsigned long long*)(smem + V_SZ + RED_FLOATS);

    const int tid = threadIdx.x;
    const int p   = tid & (PHR_PER_BLK - 1);   // phrase within block
    const int g   = tid >> 5;                  // s-group
    const int b   = blockIdx.x * PHR_PER_BLK + p;
    const uint32_t mbar_a = smem_u32(mbar);

    // ---- tid0: init mbarrier and launch TMA for the HIGH vocab half.
    // Other threads only touch the barrier after the __syncthreads below,
    // so no separate init-sync is needed.
    if (tid == 0) {
        asm volatile("mbarrier.init.shared.b64 [%0], 1;" :: "r"(mbar_a) : "memory");
        asm volatile("mbarrier.arrive.expect_tx.shared.b64 _, [%0], %1;"
                     :: "r"(mbar_a), "r"((uint32_t)HALF_BYTES) : "memory");
        uint32_t dst = smem_u32(sw + V_HALF);
        const char* src = (const char*)(w_weight + V_HALF);
#pragma unroll
        for (int c = 0; c < 2; c++) {
            asm volatile(
                "cp.async.bulk.shared::cta.global.mbarrier::complete_tx::bytes "
                "[%0], [%1], %2, [%3];"
                :: "r"(dst + c * TMA_CHUNK), "l"(src + c * TMA_CHUNK),
                   "r"((uint32_t)TMA_CHUNK), "r"(mbar_a)
                : "memory");
        }
    }

    // ---- dtype detection: int64 buffers have zero odd 32-bit words ----
    const unsigned int* __restrict__ t32 = (const unsigned int*)text_raw;
    unsigned int probe = t32[2 * (tid & 31) + 1];
    const bool is64 = __all_sync(0xffffffffu, probe == 0u);

    // s-groups 0..7 take 7 tokens, 8..31 take 6  (8*7 + 24*6 = 200)
    const int cnt = (g < 8) ? 7 : 6;
    const int s0  = (g < 8) ? g * 7 : 56 + (g - 8) * 6;

    // ---- front-batch the coalesced index loads (overlap everything) ----
    int idx[7];
    if (is64) {
        const long long* __restrict__ t = (const long long*)text_raw;
#pragma unroll
        for (int i = 0; i < 7; i++)
            if (i < cnt) idx[i] = (int)t[(size_t)(s0 + i) * B_PHR + b];
    } else {
        const int* __restrict__ t = (const int*)text_raw;
#pragma unroll
        for (int i = 0; i < 7; i++)
            if (i < cnt) idx[i] = t[(s0 + i) * B_PHR + b];
    }

    // ---- manual vectorized fill of the LOW vocab half (LSU pipe,
    //      concurrent with the TMA stream filling the high half) ----
    {
        const float4* __restrict__ w4 = (const float4*)w_weight;
        float4* s4 = (float4*)sw;
#pragma unroll 7
        for (int i = tid; i < V_HALF / 4; i += NTHR)   // 6250 float4
            s4[i] = w4[i];
    }
    __syncthreads();   // low half visible (also orders mbarrier init)

    // ---- pass A: gather tokens in the low half (TMA still streaming) ----
    float acc = 0.0f;
#pragma unroll
    for (int i = 0; i < 7; i++)
        if (i < cnt && idx[i] < V_HALF) acc += sw[idx[i]];

    // ---- wait for the TMA half, then pass B ----
    {
        uint32_t done;
        asm volatile(
            "{\n\t.reg .pred P;\n\t"
            "mbarrier.try_wait.parity.acquire.cta.shared::cta.b64 P, [%1], 0;\n\t"
            "selp.b32 %0, 1, 0, P;\n\t}"
            : "=r"(done) : "r"(mbar_a) : "memory");
        if (!done) {
            asm volatile(
                "{\n\t.reg .pred P;\n\t"
                "WL_%=:\n\t"
                "mbarrier.try_wait.parity.acquire.cta.shared::cta.b64 P, [%0], 0, 0x989680;\n\t"
                "@P bra.uni WD_%=;\n\t"
                "bra.uni WL_%=;\n\t"
                "WD_%=:\n\t}"
                :: "r"(mbar_a) : "memory");
        }
    }

#pragma unroll
    for (int i = 0; i < 7; i++)
        if (i < cnt && idx[i] >= V_HALF) acc += sw[idx[i]];

    // ---- reduce 32 partials per phrase ----
    red[g * PHR_PER_BLK + p] = acc;
    __syncthreads();

    if (tid < PHR_PER_BLK) {
        float sum = 0.0f;
#pragma unroll
        for (int j = 0; j < NGRP; j++) sum += red[j * PHR_PER_BLK + tid];
        out[blockIdx.x * PHR_PER_BLK + tid] = sum + __ldg(w_bias);
    }
}

extern "C" void kernel_launch(void* const* d_in, const int* in_sizes, int n_in,
                              void* d_out, int out_size) {
    const void*  text   = d_in[0];                 // (200, 2048) int32 or int64
    const float* weight = (const float*)d_in[1];   // (1, 50000) float32
    const float* bias   = (const float*)d_in[2];   // (1,) float32
    float*       out    = (float*)d_out;           // (2048, 1) float32

    cudaFuncSetAttribute(MNB_455266533601_kernel,
                         cudaFuncAttributeMaxDynamicSharedMemorySize, SMEM_BYTES);

    MNB_455266533601_kernel<<<NBLK, NTHR, SMEM_BYTES>>>(text, weight, bias, out);
}

// round 8
// speedup vs baseline: 1.2593x; 1.2593x over previous
#include <cuda_runtime.h>
#include <stdint.h>

// out[b] = sum_{s=0}^{199} w_weight[text[s,b]] + bias
// text (200, 2048) row-major, tokens in [0, 50000)
#define S_TOK 200
#define B_PHR 2048
#define V_SZ  50000
#define NCHUNK 4
#define CH_FLOATS (V_SZ / NCHUNK)       // 12500 floats
#define CH_BYTES  (CH_FLOATS * 4)       // 50000 B (16B multiple)
#define PHR_PER_BLK 32
#define NBLK (B_PHR / PHR_PER_BLK)      // 64 blocks, single wave
#define NTHR 1024
#define NGRP 32
#define RED_FLOATS (NGRP * PHR_PER_BLK) // 1024
// smem: table + reduction + 4 mbarriers
#define SMEM_BYTES (V_SZ * 4 + RED_FLOATS * 4 + NCHUNK * 8 + 8)

__device__ __forceinline__ uint32_t smem_u32(const void* p) {
    uint32_t a;
    asm("{ .reg .u64 t; cvta.to.shared.u64 t, %1; cvt.u32.u64 %0, t; }"
        : "=r"(a) : "l"(p));
    return a;
}

__device__ __forceinline__ void mbar_wait0(uint32_t mbar_a) {
    uint32_t done;
    asm volatile(
        "{\n\t.reg .pred P;\n\t"
        "mbarrier.try_wait.parity.acquire.cta.shared::cta.b64 P, [%1], 0;\n\t"
        "selp.b32 %0, 1, 0, P;\n\t}"
        : "=r"(done) : "r"(mbar_a) : "memory");
    if (!done) {
        asm volatile(
            "{\n\t.reg .pred P;\n\t"
            "WL_%=:\n\t"
            "mbarrier.try_wait.parity.acquire.cta.shared::cta.b64 P, [%0], 0, 0x989680;\n\t"
            "@P bra.uni WD_%=;\n\t"
            "bra.uni WL_%=;\n\t"
            "WD_%=:\n\t}"
            :: "r"(mbar_a) : "memory");
    }
}

__global__ __launch_bounds__(NTHR, 1) void MNB_455266533601_kernel(
    const void* __restrict__ text_raw,
    const float* __restrict__ w_weight,
    const float* __restrict__ w_bias,
    float* __restrict__ out)
{
    extern __shared__ float smem[];
    float* sw  = smem;                     // [V_SZ] staged table
    float* red = smem + V_SZ;              // [NGRP][PHR_PER_BLK]
    unsigned long long* mbar =
        (unsigned long long*)(smem + V_SZ + RED_FLOATS);   // [NCHUNK]

    const int tid = threadIdx.x;
    const int p   = tid & (PHR_PER_BLK - 1);   // phrase within block
    const int g   = tid >> 5;                  // s-group
    const int b   = blockIdx.x * PHR_PER_BLK + p;
    const uint32_t mbar0_a = smem_u32(mbar);

    // ---- init the 4 chunk mbarriers; sync so no thread waits pre-init ----
    if (tid == 0) {
#pragma unroll
        for (int c = 0; c < NCHUNK; c++)
            asm volatile("mbarrier.init.shared.b64 [%0], 1;"
                         :: "r"(mbar0_a + 8 * c) : "memory");
    }
    __syncthreads();

    // ---- tid0 launches the 4 TMA chunks (each signals its own barrier) ----
    if (tid == 0) {
        uint32_t dst = smem_u32(sw);
        const char* src = (const char*)w_weight;
#pragma unroll
        for (int c = 0; c < NCHUNK; c++) {
            asm volatile("mbarrier.arrive.expect_tx.shared.b64 _, [%0], %1;"
                         :: "r"(mbar0_a + 8 * c), "r"((uint32_t)CH_BYTES) : "memory");
            asm volatile(
                "cp.async.bulk.shared::cta.global.mbarrier::complete_tx::bytes "
                "[%0], [%1], %2, [%3];"
                :: "r"(dst + c * CH_BYTES), "l"(src + (size_t)c * CH_BYTES),
                   "r"((uint32_t)CH_BYTES), "r"(mbar0_a + 8 * c)
                : "memory");
        }
    }

    // ---- dtype detection: int64 buffers have zero odd 32-bit words ----
    const unsigned int* __restrict__ t32 = (const unsigned int*)text_raw;
    unsigned int probe = t32[2 * (tid & 31) + 1];
    const bool is64 = __all_sync(0xffffffffu, probe == 0u);

    // s-groups 0..7 take 7 tokens, 8..31 take 6  (8*7 + 24*6 = 200)
    const int cnt = (g < 8) ? 7 : 6;
    const int s0  = (g < 8) ? g * 7 : 56 + (g - 8) * 6;

    // ---- front-batched coalesced index loads (overlap the TMA stream) ----
    int idx[7];
    if (is64) {
        const long long* __restrict__ t = (const long long*)text_raw;
#pragma unroll
        for (int i = 0; i < 7; i++)
            if (i < cnt) idx[i] = (int)t[(size_t)(s0 + i) * B_PHR + b];
    } else {
        const int* __restrict__ t = (const int*)text_raw;
#pragma unroll
        for (int i = 0; i < 7; i++)
            if (i < cnt) idx[i] = t[(s0 + i) * B_PHR + b];
    }

    float bias = __ldg(w_bias);

    // ---- pipelined gather: pass c fires as soon as chunk c lands ----
    float acc = 0.0f;
#pragma unroll
    for (int c = 0; c < NCHUNK; c++) {
        mbar_wait0(mbar0_a + 8 * c);
#pragma unroll
        for (int i = 0; i < 7; i++) {
            if (i < cnt) {
                unsigned int off = (unsigned int)idx[i] - (unsigned int)(c * CH_FLOATS);
                if (off < (unsigned int)CH_FLOATS) acc += sw[idx[i]];
            }
        }
    }

    // ---- reduce 32 partials per phrase ----
    red[g * PHR_PER_BLK + p] = acc;
    __syncthreads();

    if (tid < PHR_PER_BLK) {
        float sum = 0.0f;
#pragma unroll
        for (int j = 0; j < NGRP; j++) sum += red[j * PHR_PER_BLK + tid];
        out[blockIdx.x * PHR_PER_BLK + tid] = sum + bias;
    }
}

extern "C" void kernel_launch(void* const* d_in, const int* in_sizes, int n_in,
                              void* d_out, int out_size) {
    const void*  text   = d_in[0];                 // (200, 2048) int32 or int64
    const float* weight = (const float*)d_in[1];   // (1, 50000) float32
    const float* bias   = (const float*)d_in[2];   // (1,) float32
    float*       out    = (float*)d_out;           // (2048, 1) float32

    cudaFuncSetAttribute(MNB_455266533601_kernel,
                         cudaFuncAttributeMaxDynamicSharedMemorySize, SMEM_BYTES);

    MNB_455266533601_kernel<<<NBLK, NTHR, SMEM_BYTES>>>(text, weight, bias, out);
}

// round 9
// speedup vs baseline: 1.3077x; 1.0385x over previous
#include <cuda_runtime.h>
#include <stdint.h>

// out[b] = sum_{s=0}^{199} w_weight[text[s,b]] + bias
// text (200, 2048) row-major, tokens in [0, 50000)
#define S_TOK 200
#define B_PHR 2048
#define V_SZ  50000
#define V_HALF 25000                    // two TMA chunks of 100KB
#define HALF_BYTES (V_HALF * 4)         // 100000 B (16B multiple)
#define PHR_PER_BLK 32
#define NBLK (B_PHR / PHR_PER_BLK)      // 64 blocks, single wave
#define NTHR 1024
#define NGRP 32
#define RED_FLOATS (NGRP * PHR_PER_BLK) // 1024
#define SMEM_BYTES (V_SZ * 4 + RED_FLOATS * 4 + 2 * 8 + 8)

__device__ __forceinline__ uint32_t smem_u32(const void* p) {
    uint32_t a;
    asm("{ .reg .u64 t; cvta.to.shared.u64 t, %1; cvt.u32.u64 %0, t; }"
        : "=r"(a) : "l"(p));
    return a;
}

__device__ __forceinline__ void mbar_wait0(uint32_t mbar_a) {
    uint32_t done;
    asm volatile(
        "{\n\t.reg .pred P;\n\t"
        "mbarrier.try_wait.parity.acquire.cta.shared::cta.b64 P, [%1], 0;\n\t"
        "selp.b32 %0, 1, 0, P;\n\t}"
        : "=r"(done) : "r"(mbar_a) : "memory");
    if (!done) {
        asm volatile(
            "{\n\t.reg .pred P;\n\t"
            "WL_%=:\n\t"
            "mbarrier.try_wait.parity.acquire.cta.shared::cta.b64 P, [%0], 0, 0x989680;\n\t"
            "@P bra.uni WD_%=;\n\t"
            "bra.uni WL_%=;\n\t"
            "WD_%=:\n\t}"
            :: "r"(mbar_a) : "memory");
    }
}

__global__ __launch_bounds__(NTHR, 1) void MNB_455266533601_kernel(
    const void* __restrict__ text_raw,
    const float* __restrict__ w_weight,
    const float* __restrict__ w_bias,
    float* __restrict__ out)
{
    extern __shared__ float smem[];
    float* sw  = smem;                     // [V_SZ] staged table
    float* red = smem + V_SZ;              // [NGRP][PHR_PER_BLK]
    unsigned long long* mbar =
        (unsigned long long*)(smem + V_SZ + RED_FLOATS);   // [2]

    const int tid = threadIdx.x;
    const int p   = tid & (PHR_PER_BLK - 1);   // phrase within block
    const int g   = tid >> 5;                  // s-group
    const int b   = blockIdx.x * PHR_PER_BLK + p;
    const uint32_t mbar0_a = smem_u32(mbar);

    // ---- init both mbarriers, one sync, then issue both TMA chunks ----
    if (tid == 0) {
        asm volatile("mbarrier.init.shared.b64 [%0], 1;" :: "r"(mbar0_a) : "memory");
        asm volatile("mbarrier.init.shared.b64 [%0], 1;" :: "r"(mbar0_a + 8) : "memory");
    }
    __syncthreads();   // init visible to all waiters (and to the TMA completes)

    if (tid == 0) {
        uint32_t dst = smem_u32(sw);
        const char* src = (const char*)w_weight;
#pragma unroll
        for (int c = 0; c < 2; c++) {
            asm volatile("mbarrier.arrive.expect_tx.shared.b64 _, [%0], %1;"
                         :: "r"(mbar0_a + 8 * c), "r"((uint32_t)HALF_BYTES) : "memory");
            asm volatile(
                "cp.async.bulk.shared::cta.global.mbarrier::complete_tx::bytes "
                "[%0], [%1], %2, [%3];"
                :: "r"(dst + c * HALF_BYTES), "l"(src + (size_t)c * HALF_BYTES),
                   "r"((uint32_t)HALF_BYTES), "r"(mbar0_a + 8 * c)
                : "memory");
        }
    }

    // ---- dtype detection: int64 buffers have zero odd 32-bit words ----
    const unsigned int* __restrict__ t32 = (const unsigned int*)text_raw;
    unsigned int probe = t32[2 * (tid & 31) + 1];
    const bool is64 = __all_sync(0xffffffffu, probe == 0u);

    // s-groups 0..7 take 7 tokens, 8..31 take 6  (8*7 + 24*6 = 200)
    const int cnt = (g < 8) ? 7 : 6;
    const int s0  = (g < 8) ? g * 7 : 56 + (g - 8) * 6;

    // ---- front-batched coalesced index loads (overlap the TMA stream) ----
    int idx[7];
    if (is64) {
        const long long* __restrict__ t = (const long long*)text_raw;
#pragma unroll
        for (int i = 0; i < 7; i++)
            if (i < cnt) idx[i] = (int)t[(size_t)(s0 + i) * B_PHR + b];
    } else {
        const int* __restrict__ t = (const int*)text_raw;
#pragma unroll
        for (int i = 0; i < 7; i++)
            if (i < cnt) idx[i] = t[(s0 + i) * B_PHR + b];
    }

    const float bias = __ldg(w_bias);

    // ---- pass A: lower half, while the upper half is still streaming ----
    float acc = 0.0f;
    mbar_wait0(mbar0_a);
#pragma unroll
    for (int i = 0; i < 7; i++)
        if (i < cnt && idx[i] < V_HALF) acc += sw[idx[i]];

    // ---- pass B: upper half ----
    mbar_wait0(mbar0_a + 8);
#pragma unroll
    for (int i = 0; i < 7; i++)
        if (i < cnt && idx[i] >= V_HALF) acc += sw[idx[i]];

    // ---- reduce 32 partials per phrase ----
    red[g * PHR_PER_BLK + p] = acc;
    __syncthreads();

    if (tid < PHR_PER_BLK) {
        float sum = 0.0f;
#pragma unroll
        for (int j = 0; j < NGRP; j++) sum += red[j * PHR_PER_BLK + tid];
        out[blockIdx.x * PHR_PER_BLK + tid] = sum + bias;
    }
}

extern "C" void kernel_launch(void* const* d_in, const int* in_sizes, int n_in,
                              void* d_out, int out_size) {
    const void*  text   = d_in[0];                 // (200, 2048) int32 or int64
    const float* weight = (const float*)d_in[1];   // (1, 50000) float32
    const float* bias   = (const float*)d_in[2];   // (1,) float32
    float*       out    = (float*)d_out;           // (2048, 1) float32

    cudaFuncSetAttribute(MNB_455266533601_kernel,
                         cudaFuncAttributeMaxDynamicSharedMemorySize, SMEM_BYTES);

    MNB_455266533601_kernel<<<NBLK, NTHR, SMEM_BYTES>>>(text, weight, bias, out);
}